// round 3
// baseline (speedup 1.0000x reference)
#include <cuda_runtime.h>
#include <math.h>
#include <stdint.h>

#define OUTW 7
#define SPP 4
#define CCH 256
#define HH 128
#define WW 128
#define BB 4
#define NROI 2000
#define FIN (OUTW*OUTW*CCH)   /* 12544 */
#define FC 1024
#define NBIN (OUTW*OUTW)      /* 49 */

// ---------------- scratch (static device globals; no dynamic alloc) ----------
__device__ float g_dataT[(size_t)BB*HH*WW*CCH];      // [B,H,W,C]   64 MB
__device__ float g_xf[(size_t)NROI*FIN];             // pooled feats [n][bin*256+c]
__device__ float g_h1[(size_t)NROI*FC];
__device__ float g_m1[(size_t)NROI*FC];
__device__ float g_h2[(size_t)NROI*FC];
__device__ float g_off[(size_t)NROI*2*NBIN];
__device__ float g_mask[(size_t)NROI*NBIN];
__device__ float g_w1p[(size_t)FIN*FC];              // permuted+tf32 w1
__device__ float g_mw1p[(size_t)FIN*FC];             // permuted+tf32 mw1
__device__ float g_w2t[(size_t)FC*FC];               // tf32 w2

// ---------------- tf32 helpers ------------------------------------------------
__device__ __forceinline__ uint32_t f2tf32(float x) {
    uint32_t u;
    asm("cvt.rna.tf32.f32 %0, %1;" : "=r"(u) : "f"(x));
    return u;
}
__device__ __forceinline__ float tf32r(float x) { return __uint_as_float(f2tf32(x)); }

__device__ __forceinline__ void mma_tf32(float* c, const uint32_t* a, const uint32_t* b) {
    asm volatile(
        "mma.sync.aligned.m16n8k8.row.col.f32.tf32.tf32.f32 "
        "{%0,%1,%2,%3}, {%4,%5,%6,%7}, {%8,%9}, {%0,%1,%2,%3};"
        : "+f"(c[0]), "+f"(c[1]), "+f"(c[2]), "+f"(c[3])
        : "r"(a[0]), "r"(a[1]), "r"(a[2]), "r"(a[3]), "r"(b[0]), "r"(b[1]));
}

__device__ __forceinline__ void cp_async16(uint32_t dst, const void* src, bool pred) {
    int sz = pred ? 16 : 0;
    asm volatile("cp.async.cg.shared.global [%0], [%1], 16, %2;\n"
                 :: "r"(dst), "l"(src), "r"(sz));
}
__device__ __forceinline__ void cp_commit() {
    asm volatile("cp.async.commit_group;\n" ::: "memory");
}
template <int N>
__device__ __forceinline__ void cp_wait() {
    asm volatile("cp.async.wait_group %0;\n" :: "n"(N) : "memory");
}

// ---------------- transpose [B,C,H,W] -> [B,H,W,C] ---------------------------
__global__ void k_transpose(const float* __restrict__ data) {
    __shared__ float tile[32][33];
    int xt = blockIdx.x;
    int by = blockIdx.y;
    int ct = blockIdx.z;
    int b = by >> 7, y = by & 127;
    int x0 = xt * 32, c0 = ct * 32;
    int tx = threadIdx.x, ty = threadIdx.y;
#pragma unroll
    for (int i = 0; i < 4; i++) {
        int c = c0 + ty + 8 * i;
        tile[ty + 8 * i][tx] =
            data[(((size_t)b * CCH + c) * HH + y) * WW + x0 + tx];
    }
    __syncthreads();
#pragma unroll
    for (int i = 0; i < 4; i++) {
        int x = x0 + ty + 8 * i;
        g_dataT[(((size_t)b * HH + y) * WW + x) * CCH + c0 + tx] =
            tile[tx][ty + 8 * i];
    }
}

// ---------------- weight prep: permute rows of w1/mw1, round to tf32 ---------
__global__ void k_wprep(const float* __restrict__ w1, const float* __restrict__ mw1) {
    int row = blockIdx.x;               // dst row = bin*256 + c
    int c = row & 255, bin = row >> 8;
    int src = c * NBIN + bin;
    const float4* s1 = (const float4*)(w1  + (size_t)src * FC);
    const float4* s2 = (const float4*)(mw1 + (size_t)src * FC);
    float4* d1 = (float4*)(g_w1p  + (size_t)row * FC);
    float4* d2 = (float4*)(g_mw1p + (size_t)row * FC);
    int i = threadIdx.x;                // 256 threads x float4 = 1024
    float4 v = s1[i];
    v.x = tf32r(v.x); v.y = tf32r(v.y); v.z = tf32r(v.z); v.w = tf32r(v.w);
    d1[i] = v;
    v = s2[i];
    v.x = tf32r(v.x); v.y = tf32r(v.y); v.z = tf32r(v.z); v.w = tf32r(v.w);
    d2[i] = v;
}

__global__ void k_w2cvt(const float* __restrict__ w2) {
    int row = blockIdx.x;
    const float4* s = (const float4*)(w2 + (size_t)row * FC);
    float4* d = (float4*)(g_w2t + (size_t)row * FC);
    int i = threadIdx.x;
    float4 v = s[i];
    v.x = tf32r(v.x); v.y = tf32r(v.y); v.z = tf32r(v.z); v.w = tf32r(v.w);
    d[i] = v;
}

// ---------------- deform ROI pool with per-bin cell dedup ---------------------
// pass 1: out = xf, layout [n][bin*256+c], values tf32-rounded.
// pass 2: out = d_out, layout [n][c*49+bin], multiplied by mask.
__global__ void __launch_bounds__(256) k_pool(
        const float* __restrict__ rois,
        const float* __restrict__ offset,
        const float* __restrict__ mask,
        float* __restrict__ out, int pass) {
    int bidx = blockIdx.x;
    int n = bidx / NBIN;
    int bin = bidx % NBIN;
    int ph = bin / OUTW, pw = bin % OUTW;
    int tid = threadIdx.x;

    __shared__ float scell[36 * 256];
    __shared__ int   sc00[16], sc01[16], sc10[16], sc11[16];
    __shared__ float sdx[16], sdy[16], sval[16];
    __shared__ int   sb, sgx, sgy;
    __shared__ unsigned long long smask;

    const float* r = rois + n * 5;
    if (tid < 16) {
        float sw = floorf(r[1] + 0.5f) * 0.0625f - 0.5f;
        float sh = floorf(r[2] + 0.5f) * 0.0625f - 0.5f;
        float ew = (floorf(r[3] + 0.5f) + 1.0f) * 0.0625f - 0.5f;
        float eh = (floorf(r[4] + 0.5f) + 1.0f) * 0.0625f - 0.5f;
        float rw = fmaxf(ew - sw, 0.1f);
        float rh = fmaxf(eh - sh, 0.1f);
        float bw = rw / 7.0f, bh = rh / 7.0f;
        float subw = bw / 4.0f, subh = bh / 4.0f;
        float ws0 = (float)pw * bw + sw;
        float hs0 = (float)ph * bh + sh;
        if (pass == 2) {
            ws0 += offset[(size_t)n * 98 + bin] * 0.1f * rw;
            hs0 += offset[(size_t)n * 98 + 49 + bin] * 0.1f * rh;
        }
        int ix = tid & 3, iy = tid >> 2;
        float w = ws0 + (float)ix * subw;
        float h = hs0 + (float)iy * subh;
        bool valid = (w >= -0.5f) && (w <= (float)WW - 0.5f) &&
                     (h >= -0.5f) && (h <= (float)HH - 0.5f);
        float wc = fminf(fmaxf(w, 0.0f), (float)(WW - 1));
        float hc = fminf(fmaxf(h, 0.0f), (float)(HH - 1));
        int x0 = (int)floorf(wc);
        int y0 = (int)floorf(hc);
        int x1 = min(x0 + 1, WW - 1);
        int y1 = min(y0 + 1, HH - 1);
        // min-reduce over the 16 leader lanes for window origin
        int gx = x0, gy = y0;
#pragma unroll
        for (int o = 8; o >= 1; o >>= 1) {
            gx = min(gx, __shfl_xor_sync(0xFFFFu, gx, o));
            gy = min(gy, __shfl_xor_sync(0xFFFFu, gy, o));
        }
        int c00 = (y0 - gy) * 6 + (x0 - gx);
        int c01 = (y0 - gy) * 6 + (x1 - gx);
        int c10 = (y1 - gy) * 6 + (x0 - gx);
        int c11 = (y1 - gy) * 6 + (x1 - gx);
        sc00[tid] = c00; sc01[tid] = c01; sc10[tid] = c10; sc11[tid] = c11;
        sdx[tid] = wc - (float)x0;
        sdy[tid] = hc - (float)y0;
        sval[tid] = valid ? 1.0f : 0.0f;
        unsigned long long m = 0ull;
        if (valid)
            m = (1ull << c00) | (1ull << c01) | (1ull << c10) | (1ull << c11);
#pragma unroll
        for (int o = 8; o >= 1; o >>= 1)
            m |= __shfl_xor_sync(0xFFFFu, m, o);
        if (tid == 0) { smask = m; sgx = gx; sgy = gy; sb = (int)r[0]; }
    }
    __syncthreads();

    unsigned long long m = smask;
    const float* base = g_dataT + (size_t)sb * (HH * WW * CCH);
    int gx = sgx, gy = sgy;
#pragma unroll
    for (int cell = 0; cell < 36; cell++) {
        if ((m >> cell) & 1ull) {
            int y = gy + cell / 6, x = gx + cell % 6;
            scell[cell * 256 + tid] = base[((size_t)(y * WW + x)) * CCH + tid];
        }
    }
    __syncthreads();

    float cnt = 0.0f;
#pragma unroll
    for (int s = 0; s < 16; s++) cnt += sval[s];

    float acc = 0.0f;
#pragma unroll
    for (int s = 0; s < 16; s++) {
        if (sval[s] > 0.0f) {
            float dx = sdx[s], dy = sdy[s];
            float v00 = scell[sc00[s] * 256 + tid];
            float v01 = scell[sc01[s] * 256 + tid];
            float v10 = scell[sc10[s] * 256 + tid];
            float v11 = scell[sc11[s] * 256 + tid];
            acc += (1.0f - dx) * (1.0f - dy) * v00 + dx * (1.0f - dy) * v01 +
                   (1.0f - dx) * dy * v10 + dx * dy * v11;
        }
    }
    float v = (cnt > 0.0f) ? acc / cnt : 0.0f;
    if (pass == 2) {
        v *= mask[(size_t)n * NBIN + bin];
        out[(size_t)n * FIN + (size_t)tid * NBIN + bin] = v;
    } else {
        out[(size_t)n * FIN + (size_t)bin * 256 + tid] = tf32r(v);
    }
}

// ---------------- tf32 tensor-core GEMM (cp.async double-buffered) ------------
// A [M,K] row-major (tf32-rounded), B [K,N] row-major (tf32-rounded).
// K%16==0, N%128==0. gridDim.z==2 selects B2/bias2/C2 head.
#define LDA_S 20
#define LDB_S 136
__global__ void __launch_bounds__(256, 2) k_gemm_tf32(
    const float* __restrict__ A, int lda,
    const float* __restrict__ B, int ldb,
    const float* __restrict__ bias,
    float* __restrict__ C, int ldc,
    const float* __restrict__ B2,
    const float* __restrict__ bias2,
    float* __restrict__ C2,
    int M, int N, int K, int act, int cvt_out) {
    if (blockIdx.z == 1) { B = B2; bias = bias2; C = C2; }

    __shared__ float As[2][128 * LDA_S];
    __shared__ float Bs[2][16 * LDB_S];

    int tid = threadIdx.x;
    int warp = tid >> 5, lane = tid & 31;
    int g = lane >> 2, t = lane & 3;
    int wm = warp >> 2;       // 0..1
    int wn = warp & 3;        // 0..3
    int bm = blockIdx.y * 128, bn = blockIdx.x * 128;

    int arow = tid >> 2;              // 0..63
    int akc  = (tid & 3) * 4;
    int bkr  = tid >> 5;              // 0..7
    int bn4  = lane * 4;

    const float* Ap0 = A + (size_t)(bm + arow) * lda + akc;
    const float* Ap1 = A + (size_t)(bm + arow + 64) * lda + akc;
    bool am0 = (bm + arow) < M;
    bool am1 = (bm + arow + 64) < M;
    const float* Bp0 = B + (size_t)bkr * ldb + bn + bn4;
    const float* Bp1 = B + (size_t)(bkr + 8) * ldb + bn + bn4;

    uint32_t sa0[2], sa1[2], sb0[2], sb1[2];
#pragma unroll
    for (int s = 0; s < 2; s++) {
        sa0[s] = (uint32_t)__cvta_generic_to_shared(&As[s][arow * LDA_S + akc]);
        sa1[s] = (uint32_t)__cvta_generic_to_shared(&As[s][(arow + 64) * LDA_S + akc]);
        sb0[s] = (uint32_t)__cvta_generic_to_shared(&Bs[s][bkr * LDB_S + bn4]);
        sb1[s] = (uint32_t)__cvta_generic_to_shared(&Bs[s][(bkr + 8) * LDB_S + bn4]);
    }

    float acc[4][4][4];
#pragma unroll
    for (int i = 0; i < 4; i++)
#pragma unroll
        for (int j = 0; j < 4; j++)
#pragma unroll
            for (int q = 0; q < 4; q++) acc[i][j][q] = 0.0f;

    int nt = K / 16;
    // prologue: stage 0
    cp_async16(sa0[0], Ap0, am0);
    cp_async16(sa1[0], Ap1, am1);
    cp_async16(sb0[0], Bp0, true);
    cp_async16(sb1[0], Bp1, true);
    cp_commit();

    for (int kt = 0; kt < nt; kt++) {
        int cur = kt & 1;
        if (kt + 1 < nt) {
            int k0 = (kt + 1) * 16;
            cp_async16(sa0[cur ^ 1], Ap0 + k0, am0);
            cp_async16(sa1[cur ^ 1], Ap1 + k0, am1);
            cp_async16(sb0[cur ^ 1], Bp0 + (size_t)k0 * ldb, true);
            cp_async16(sb1[cur ^ 1], Bp1 + (size_t)k0 * ldb, true);
            cp_commit();
            cp_wait<1>();
        } else {
            cp_wait<0>();
        }
        __syncthreads();

        const uint32_t* Au = (const uint32_t*)As[cur];
        const uint32_t* Bu = (const uint32_t*)Bs[cur];
#pragma unroll
        for (int ko = 0; ko < 2; ko++) {
            int kb = ko * 8;
            uint32_t af[4][4], bf[4][2];
#pragma unroll
            for (int i = 0; i < 4; i++) {
                int m0 = wm * 64 + i * 16;
                af[i][0] = Au[(m0 + g) * LDA_S + kb + t];
                af[i][1] = Au[(m0 + g + 8) * LDA_S + kb + t];
                af[i][2] = Au[(m0 + g) * LDA_S + kb + t + 4];
                af[i][3] = Au[(m0 + g + 8) * LDA_S + kb + t + 4];
            }
#pragma unroll
            for (int j = 0; j < 4; j++) {
                int n0 = wn * 32 + j * 8;
                bf[j][0] = Bu[(kb + t) * LDB_S + n0 + g];
                bf[j][1] = Bu[(kb + t + 4) * LDB_S + n0 + g];
            }
#pragma unroll
            for (int i = 0; i < 4; i++)
#pragma unroll
                for (int j = 0; j < 4; j++)
                    mma_tf32(acc[i][j], af[i], bf[j]);
        }
        __syncthreads();
    }

    // epilogue
#pragma unroll
    for (int i = 0; i < 4; i++) {
        int r0 = bm + wm * 64 + i * 16 + g;
        int r1 = r0 + 8;
#pragma unroll
        for (int j = 0; j < 4; j++) {
            int c0 = bn + wn * 32 + j * 8 + 2 * t;
            float bv0 = bias[c0], bv1 = bias[c0 + 1];
            float vv[4] = {acc[i][j][0] + bv0, acc[i][j][1] + bv1,
                           acc[i][j][2] + bv0, acc[i][j][3] + bv1};
#pragma unroll
            for (int q = 0; q < 4; q++) {
                if (act == 1) vv[q] = fmaxf(vv[q], 0.0f);
                else if (act == 2) vv[q] = 1.0f / (1.0f + expf(-vv[q]));
                if (cvt_out) vv[q] = tf32r(vv[q]);
            }
            if (r0 < M) {
                C[(size_t)r0 * ldc + c0]     = vv[0];
                C[(size_t)r0 * ldc + c0 + 1] = vv[1];
            }
            if (r1 < M) {
                C[(size_t)r1 * ldc + c0]     = vv[2];
                C[(size_t)r1 * ldc + c0 + 1] = vv[3];
            }
        }
    }
}

// ---------------- small-N head GEMM: C = act(A @ B + bias) --------------------
// A [2000,1024] row-major, B [1024,N], N<=128. 8 rows per block.
__global__ void __launch_bounds__(256) k_head(
        const float* __restrict__ A, const float* __restrict__ B,
        const float* __restrict__ bias, float* __restrict__ C,
        int N, int act) {
    __shared__ float Asm[8 * FC];
    int tid = threadIdx.x;
    int m0 = blockIdx.x * 8;
    const float4* Af = (const float4*)(A + (size_t)m0 * FC);
    float4* Sf = (float4*)Asm;
#pragma unroll
    for (int i = 0; i < 8; i++) Sf[tid + 256 * i] = Af[tid + 256 * i];
    __syncthreads();

    int row = tid >> 5, lane = tid & 31;
    float acc[4] = {0.f, 0.f, 0.f, 0.f};
    const float* ar = Asm + row * FC;
    for (int k = 0; k < FC; k += 2) {
        float a0 = ar[k], a1 = ar[k + 1];
        const float* bk0 = B + (size_t)k * N;
        const float* bk1 = bk0 + N;
#pragma unroll
        for (int j = 0; j < 4; j++) {
            int col = lane + 32 * j;
            if (col < N) {
                acc[j] += a0 * bk0[col];
                acc[j] += a1 * bk1[col];
            }
        }
    }
#pragma unroll
    for (int j = 0; j < 4; j++) {
        int col = lane + 32 * j;
        if (col < N) {
            float v = acc[j] + bias[col];
            if (act == 1) v = fmaxf(v, 0.0f);
            else if (act == 2) v = 1.0f / (1.0f + expf(-v));
            C[(size_t)(m0 + row) * N + col] = v;
        }
    }
}

// ---------------- launch ------------------------------------------------------
extern "C" void kernel_launch(void* const* d_in, const int* in_sizes, int n_in,
                              void* d_out, int out_size) {
    const float* data = (const float*)d_in[0];
    const float* rois = (const float*)d_in[1];
    const float* w1   = (const float*)d_in[2];
    const float* b1   = (const float*)d_in[3];
    const float* w2   = (const float*)d_in[4];
    const float* b2   = (const float*)d_in[5];
    const float* w3   = (const float*)d_in[6];
    const float* b3   = (const float*)d_in[7];
    const float* mw1  = (const float*)d_in[8];
    const float* mb1  = (const float*)d_in[9];
    const float* mw2  = (const float*)d_in[10];
    const float* mb2  = (const float*)d_in[11];
    float* out = (float*)d_out;

    float *xf, *h1, *m1, *h2, *off, *maskb, *w1p, *mw1p, *w2t;
    cudaGetSymbolAddress((void**)&xf,    g_xf);
    cudaGetSymbolAddress((void**)&h1,    g_h1);
    cudaGetSymbolAddress((void**)&m1,    g_m1);
    cudaGetSymbolAddress((void**)&h2,    g_h2);
    cudaGetSymbolAddress((void**)&off,   g_off);
    cudaGetSymbolAddress((void**)&maskb, g_mask);
    cudaGetSymbolAddress((void**)&w1p,   g_w1p);
    cudaGetSymbolAddress((void**)&mw1p,  g_mw1p);
    cudaGetSymbolAddress((void**)&w2t,   g_w2t);

    // 1. layout transform + weight prep
    k_transpose<<<dim3(4, 512, 8), dim3(32, 8)>>>(data);
    k_wprep<<<FIN, 256>>>(w1, mw1);
    k_w2cvt<<<FC, 256>>>(w2);

    // 2. pool pass 1 -> xf [n][bin*256+c] (tf32-rounded)
    k_pool<<<NROI * NBIN, 256>>>(rois, nullptr, nullptr, xf, 1);

    // 3. G1 fused: xf @ w1p -> h1 (relu) | xf @ mw1p -> m1 (relu)
    k_gemm_tf32<<<dim3(FC / 128, (NROI + 127) / 128, 2), 256>>>(
        xf, FIN, w1p, FC, b1, h1, FC, mw1p, mb1, m1,
        NROI, FC, FIN, 1, 1);

    // 4. G2: h1 @ w2t -> h2 (relu)
    k_gemm_tf32<<<dim3(FC / 128, (NROI + 127) / 128, 1), 256>>>(
        h1, FC, w2t, FC, b2, h2, FC, nullptr, nullptr, nullptr,
        NROI, FC, FC, 1, 0);

    // 5. G3: h2 @ w3 -> offsets [2000,98]
    k_head<<<NROI / 8, 256>>>(h2, w3, b3, off, 98, 0);

    // 6. G4: m1 @ mw2 -> mask [2000,49] (sigmoid)
    k_head<<<NROI / 8, 256>>>(m1, mw2, mb2, maskb, 49, 2);

    // 7. pool pass 2 (offset + mask) -> d_out [N,C,7,7]
    k_pool<<<NROI * NBIN, 256>>>(rois, off, maskb, out, 2);
}

// round 4
// speedup vs baseline: 1.7535x; 1.7535x over previous
#include <cuda_runtime.h>
#include <math.h>
#include <stdint.h>

#define OUTW 7
#define SPP 4
#define CCH 256
#define HH 128
#define WW 128
#define BB 4
#define NROI 2000
#define FIN (OUTW*OUTW*CCH)   /* 12544 */
#define FC 1024
#define NBIN (OUTW*OUTW)      /* 49 */

// ---------------- scratch (static device globals; no dynamic alloc) ----------
__device__ float g_dataT[(size_t)BB*HH*WW*CCH];      // [B,H,W,C]   64 MB
__device__ float g_xf[(size_t)NROI*FIN];             // pooled feats [n][bin*256+c]
__device__ float g_h1[(size_t)NROI*FC];
__device__ float g_m1[(size_t)NROI*FC];
__device__ float g_h2[(size_t)NROI*FC];
__device__ float g_off[(size_t)NROI*2*NBIN];
__device__ float g_mask[(size_t)NROI*NBIN];
__device__ float g_w1p[(size_t)FIN*FC];              // permuted+tf32 w1
__device__ float g_mw1p[(size_t)FIN*FC];             // permuted+tf32 mw1
__device__ float g_w2t[(size_t)FC*FC];               // tf32 w2

// ---------------- tf32 helpers ------------------------------------------------
__device__ __forceinline__ uint32_t f2tf32(float x) {
    uint32_t u;
    asm("cvt.rna.tf32.f32 %0, %1;" : "=r"(u) : "f"(x));
    return u;
}
__device__ __forceinline__ float tf32r(float x) { return __uint_as_float(f2tf32(x)); }

__device__ __forceinline__ void mma_tf32(float* c, const uint32_t* a, const uint32_t* b) {
    asm volatile(
        "mma.sync.aligned.m16n8k8.row.col.f32.tf32.tf32.f32 "
        "{%0,%1,%2,%3}, {%4,%5,%6,%7}, {%8,%9}, {%0,%1,%2,%3};"
        : "+f"(c[0]), "+f"(c[1]), "+f"(c[2]), "+f"(c[3])
        : "r"(a[0]), "r"(a[1]), "r"(a[2]), "r"(a[3]), "r"(b[0]), "r"(b[1]));
}

__device__ __forceinline__ void cp_async16(uint32_t dst, const void* src, bool pred) {
    int sz = pred ? 16 : 0;
    asm volatile("cp.async.cg.shared.global [%0], [%1], 16, %2;\n"
                 :: "r"(dst), "l"(src), "r"(sz));
}
__device__ __forceinline__ void cp_commit() {
    asm volatile("cp.async.commit_group;\n" ::: "memory");
}
template <int N>
__device__ __forceinline__ void cp_wait() {
    asm volatile("cp.async.wait_group %0;\n" :: "n"(N) : "memory");
}

// ---------------- transpose [B,C,H,W] -> [B,H,W,C] ---------------------------
__global__ void k_transpose(const float* __restrict__ data) {
    __shared__ float tile[32][33];
    int xt = blockIdx.x;
    int by = blockIdx.y;
    int ct = blockIdx.z;
    int b = by >> 7, y = by & 127;
    int x0 = xt * 32, c0 = ct * 32;
    int tx = threadIdx.x, ty = threadIdx.y;
#pragma unroll
    for (int i = 0; i < 4; i++) {
        int c = c0 + ty + 8 * i;
        tile[ty + 8 * i][tx] =
            data[(((size_t)b * CCH + c) * HH + y) * WW + x0 + tx];
    }
    __syncthreads();
#pragma unroll
    for (int i = 0; i < 4; i++) {
        int x = x0 + ty + 8 * i;
        g_dataT[(((size_t)b * HH + y) * WW + x) * CCH + c0 + tx] =
            tile[tx][ty + 8 * i];
    }
}

// ---------------- weight prep: permute rows of w1/mw1, round to tf32 ---------
__global__ void k_wprep(const float* __restrict__ w1, const float* __restrict__ mw1) {
    int row = blockIdx.x;               // dst row = bin*256 + c
    int c = row & 255, bin = row >> 8;
    int src = c * NBIN + bin;
    const float4* s1 = (const float4*)(w1  + (size_t)src * FC);
    const float4* s2 = (const float4*)(mw1 + (size_t)src * FC);
    float4* d1 = (float4*)(g_w1p  + (size_t)row * FC);
    float4* d2 = (float4*)(g_mw1p + (size_t)row * FC);
    int i = threadIdx.x;
    float4 v = s1[i];
    v.x = tf32r(v.x); v.y = tf32r(v.y); v.z = tf32r(v.z); v.w = tf32r(v.w);
    d1[i] = v;
    v = s2[i];
    v.x = tf32r(v.x); v.y = tf32r(v.y); v.z = tf32r(v.z); v.w = tf32r(v.w);
    d2[i] = v;
}

__global__ void k_w2cvt(const float* __restrict__ w2) {
    int row = blockIdx.x;
    const float4* s = (const float4*)(w2 + (size_t)row * FC);
    float4* d = (float4*)(g_w2t + (size_t)row * FC);
    int i = threadIdx.x;
    float4 v = s[i];
    v.x = tf32r(v.x); v.y = tf32r(v.y); v.z = tf32r(v.z); v.w = tf32r(v.w);
    d[i] = v;
}

// ---------------- deform ROI pool: per-cell weight factorization --------------
// One (roi,bin) per 64-thread block; each thread covers 4 channels (float4).
// out[c] = norm * sum_cell wcell[cell] * pix[cell][c]
// pass 1: out = xf, layout [n][bin*256+c], values tf32-rounded.
// pass 2: out = d_out, layout [n][c*49+bin], norm folds in mask.
__global__ void __launch_bounds__(64) k_pool(
        const float* __restrict__ rois,
        const float* __restrict__ offset,
        const float* __restrict__ mask,
        float* __restrict__ out, int pass) {
    int bidx = blockIdx.x;
    int n = bidx / NBIN;
    int bin = bidx % NBIN;
    int ph = bin / OUTW, pw = bin % OUTW;
    int tid = threadIdx.x;

    __shared__ float wcell[36];
    __shared__ float snorm;
    __shared__ int   sb, sgx, sgy;
    __shared__ unsigned long long smask;

    if (tid < 36) wcell[tid] = 0.0f;
    __syncthreads();

    const float* r = rois + n * 5;
    if (tid < 16) {
        float sw = floorf(r[1] + 0.5f) * 0.0625f - 0.5f;
        float sh = floorf(r[2] + 0.5f) * 0.0625f - 0.5f;
        float ew = (floorf(r[3] + 0.5f) + 1.0f) * 0.0625f - 0.5f;
        float eh = (floorf(r[4] + 0.5f) + 1.0f) * 0.0625f - 0.5f;
        float rw = fmaxf(ew - sw, 0.1f);
        float rh = fmaxf(eh - sh, 0.1f);
        float bw = rw / 7.0f, bh = rh / 7.0f;
        float subw = bw / 4.0f, subh = bh / 4.0f;
        float ws0 = (float)pw * bw + sw;
        float hs0 = (float)ph * bh + sh;
        if (pass == 2) {
            ws0 += offset[(size_t)n * 98 + bin] * 0.1f * rw;
            hs0 += offset[(size_t)n * 98 + 49 + bin] * 0.1f * rh;
        }
        int ix = tid & 3, iy = tid >> 2;
        float w = ws0 + (float)ix * subw;
        float h = hs0 + (float)iy * subh;
        bool valid = (w >= -0.5f) && (w <= (float)WW - 0.5f) &&
                     (h >= -0.5f) && (h <= (float)HH - 0.5f);
        float wc = fminf(fmaxf(w, 0.0f), (float)(WW - 1));
        float hc = fminf(fmaxf(h, 0.0f), (float)(HH - 1));
        int x0 = (int)floorf(wc);
        int y0 = (int)floorf(hc);
        int x1 = min(x0 + 1, WW - 1);
        int y1 = min(y0 + 1, HH - 1);
        // min-reduce window origin over the 16 leader lanes
        int gx = x0, gy = y0;
#pragma unroll
        for (int o = 8; o >= 1; o >>= 1) {
            gx = min(gx, __shfl_xor_sync(0xFFFFu, gx, o));
            gy = min(gy, __shfl_xor_sync(0xFFFFu, gy, o));
        }
        float dx = wc - (float)x0;
        float dy = hc - (float)y0;
        int c00 = (y0 - gy) * 6 + (x0 - gx);
        int c01 = (y0 - gy) * 6 + (x1 - gx);
        int c10 = (y1 - gy) * 6 + (x0 - gx);
        int c11 = (y1 - gy) * 6 + (x1 - gx);
        unsigned long long m = 0ull;
        float cnt = valid ? 1.0f : 0.0f;
        if (valid) {
            atomicAdd(&wcell[c00], (1.0f - dx) * (1.0f - dy));
            atomicAdd(&wcell[c01], dx * (1.0f - dy));
            atomicAdd(&wcell[c10], (1.0f - dx) * dy);
            atomicAdd(&wcell[c11], dx * dy);
            m = (1ull << c00) | (1ull << c01) | (1ull << c10) | (1ull << c11);
        }
#pragma unroll
        for (int o = 8; o >= 1; o >>= 1) {
            m |= __shfl_xor_sync(0xFFFFu, m, o);
            cnt += __shfl_xor_sync(0xFFFFu, cnt, o);
        }
        if (tid == 0) {
            smask = m; sgx = gx; sgy = gy; sb = (int)r[0];
            float norm = (cnt > 0.0f) ? 1.0f / cnt : 0.0f;
            if (pass == 2) norm *= mask[(size_t)n * NBIN + bin];
            snorm = norm;
        }
    }
    __syncthreads();

    unsigned long long m = smask;
    float norm = snorm;
    int gx = sgx, gy = sgy;
    const float4* base =
        (const float4*)(g_dataT + (size_t)sb * (HH * WW * CCH)) + tid;

    float ax = 0.f, ay = 0.f, az = 0.f, aw = 0.f;
    while (m) {
        int cell = __ffsll((long long)m) - 1;
        m &= m - 1;
        float w = wcell[cell];
        int y = gy + cell / 6;
        int x = gx + cell - (cell / 6) * 6;
        float4 v = base[(size_t)(y * WW + x) * 64];
        ax += w * v.x; ay += w * v.y; az += w * v.z; aw += w * v.w;
    }
    ax *= norm; ay *= norm; az *= norm; aw *= norm;

    if (pass == 2) {
        float* o = out + (size_t)n * FIN + (size_t)(tid * 4) * NBIN + bin;
        o[0]        = ax;
        o[NBIN]     = ay;
        o[2 * NBIN] = az;
        o[3 * NBIN] = aw;
    } else {
        float4 v = make_float4(tf32r(ax), tf32r(ay), tf32r(az), tf32r(aw));
        *(float4*)(out + (size_t)n * FIN + (size_t)bin * 256 + tid * 4) = v;
    }
}

// ---------------- tf32 tensor-core GEMM (cp.async double-buffered) ------------
#define LDA_S 20
#define LDB_S 136
__global__ void __launch_bounds__(256, 2) k_gemm_tf32(
    const float* __restrict__ A, int lda,
    const float* __restrict__ B, int ldb,
    const float* __restrict__ bias,
    float* __restrict__ C, int ldc,
    const float* __restrict__ B2,
    const float* __restrict__ bias2,
    float* __restrict__ C2,
    int M, int N, int K, int act, int cvt_out) {
    if (blockIdx.z == 1) { B = B2; bias = bias2; C = C2; }

    __shared__ float As[2][128 * LDA_S];
    __shared__ float Bs[2][16 * LDB_S];

    int tid = threadIdx.x;
    int warp = tid >> 5, lane = tid & 31;
    int g = lane >> 2, t = lane & 3;
    int wm = warp >> 2;
    int wn = warp & 3;
    int bm = blockIdx.y * 128, bn = blockIdx.x * 128;

    int arow = tid >> 2;
    int akc  = (tid & 3) * 4;
    int bkr  = tid >> 5;
    int bn4  = lane * 4;

    const float* Ap0 = A + (size_t)(bm + arow) * lda + akc;
    const float* Ap1 = A + (size_t)(bm + arow + 64) * lda + akc;
    bool am0 = (bm + arow) < M;
    bool am1 = (bm + arow + 64) < M;
    const float* Bp0 = B + (size_t)bkr * ldb + bn + bn4;
    const float* Bp1 = B + (size_t)(bkr + 8) * ldb + bn + bn4;

    uint32_t sa0[2], sa1[2], sb0[2], sb1[2];
#pragma unroll
    for (int s = 0; s < 2; s++) {
        sa0[s] = (uint32_t)__cvta_generic_to_shared(&As[s][arow * LDA_S + akc]);
        sa1[s] = (uint32_t)__cvta_generic_to_shared(&As[s][(arow + 64) * LDA_S + akc]);
        sb0[s] = (uint32_t)__cvta_generic_to_shared(&Bs[s][bkr * LDB_S + bn4]);
        sb1[s] = (uint32_t)__cvta_generic_to_shared(&Bs[s][(bkr + 8) * LDB_S + bn4]);
    }

    float acc[4][4][4];
#pragma unroll
    for (int i = 0; i < 4; i++)
#pragma unroll
        for (int j = 0; j < 4; j++)
#pragma unroll
            for (int q = 0; q < 4; q++) acc[i][j][q] = 0.0f;

    int nt = K / 16;
    cp_async16(sa0[0], Ap0, am0);
    cp_async16(sa1[0], Ap1, am1);
    cp_async16(sb0[0], Bp0, true);
    cp_async16(sb1[0], Bp1, true);
    cp_commit();

    for (int kt = 0; kt < nt; kt++) {
        int cur = kt & 1;
        if (kt + 1 < nt) {
            int k0 = (kt + 1) * 16;
            cp_async16(sa0[cur ^ 1], Ap0 + k0, am0);
            cp_async16(sa1[cur ^ 1], Ap1 + k0, am1);
            cp_async16(sb0[cur ^ 1], Bp0 + (size_t)k0 * ldb, true);
            cp_async16(sb1[cur ^ 1], Bp1 + (size_t)k0 * ldb, true);
            cp_commit();
            cp_wait<1>();
        } else {
            cp_wait<0>();
        }
        __syncthreads();

        const uint32_t* Au = (const uint32_t*)As[cur];
        const uint32_t* Bu = (const uint32_t*)Bs[cur];
#pragma unroll
        for (int ko = 0; ko < 2; ko++) {
            int kb = ko * 8;
            uint32_t af[4][4], bf[4][2];
#pragma unroll
            for (int i = 0; i < 4; i++) {
                int m0 = wm * 64 + i * 16;
                af[i][0] = Au[(m0 + g) * LDA_S + kb + t];
                af[i][1] = Au[(m0 + g + 8) * LDA_S + kb + t];
                af[i][2] = Au[(m0 + g) * LDA_S + kb + t + 4];
                af[i][3] = Au[(m0 + g + 8) * LDA_S + kb + t + 4];
            }
#pragma unroll
            for (int j = 0; j < 4; j++) {
                int n0 = wn * 32 + j * 8;
                bf[j][0] = Bu[(kb + t) * LDB_S + n0 + g];
                bf[j][1] = Bu[(kb + t + 4) * LDB_S + n0 + g];
            }
#pragma unroll
            for (int i = 0; i < 4; i++)
#pragma unroll
                for (int j = 0; j < 4; j++)
                    mma_tf32(acc[i][j], af[i], bf[j]);
        }
        __syncthreads();
    }

#pragma unroll
    for (int i = 0; i < 4; i++) {
        int r0 = bm + wm * 64 + i * 16 + g;
        int r1 = r0 + 8;
#pragma unroll
        for (int j = 0; j < 4; j++) {
            int c0 = bn + wn * 32 + j * 8 + 2 * t;
            float bv0 = bias[c0], bv1 = bias[c0 + 1];
            float vv[4] = {acc[i][j][0] + bv0, acc[i][j][1] + bv1,
                           acc[i][j][2] + bv0, acc[i][j][3] + bv1};
#pragma unroll
            for (int q = 0; q < 4; q++) {
                if (act == 1) vv[q] = fmaxf(vv[q], 0.0f);
                else if (act == 2) vv[q] = 1.0f / (1.0f + expf(-vv[q]));
                if (cvt_out) vv[q] = tf32r(vv[q]);
            }
            if (r0 < M) {
                C[(size_t)r0 * ldc + c0]     = vv[0];
                C[(size_t)r0 * ldc + c0 + 1] = vv[1];
            }
            if (r1 < M) {
                C[(size_t)r1 * ldc + c0]     = vv[2];
                C[(size_t)r1 * ldc + c0 + 1] = vv[3];
            }
        }
    }
}

// ---------------- small-N head GEMM -------------------------------------------
__global__ void __launch_bounds__(256) k_head(
        const float* __restrict__ A, const float* __restrict__ B,
        const float* __restrict__ bias, float* __restrict__ C,
        int N, int act) {
    __shared__ float Asm[8 * FC];
    int tid = threadIdx.x;
    int m0 = blockIdx.x * 8;
    const float4* Af = (const float4*)(A + (size_t)m0 * FC);
    float4* Sf = (float4*)Asm;
#pragma unroll
    for (int i = 0; i < 8; i++) Sf[tid + 256 * i] = Af[tid + 256 * i];
    __syncthreads();

    int row = tid >> 5, lane = tid & 31;
    float acc[4] = {0.f, 0.f, 0.f, 0.f};
    const float* ar = Asm + row * FC;
    for (int k = 0; k < FC; k += 2) {
        float a0 = ar[k], a1 = ar[k + 1];
        const float* bk0 = B + (size_t)k * N;
        const float* bk1 = bk0 + N;
#pragma unroll
        for (int j = 0; j < 4; j++) {
            int col = lane + 32 * j;
            if (col < N) {
                acc[j] += a0 * bk0[col];
                acc[j] += a1 * bk1[col];
            }
        }
    }
#pragma unroll
    for (int j = 0; j < 4; j++) {
        int col = lane + 32 * j;
        if (col < N) {
            float v = acc[j] + bias[col];
            if (act == 1) v = fmaxf(v, 0.0f);
            else if (act == 2) v = 1.0f / (1.0f + expf(-v));
            C[(size_t)(m0 + row) * N + col] = v;
        }
    }
}

// ---------------- launch ------------------------------------------------------
extern "C" void kernel_launch(void* const* d_in, const int* in_sizes, int n_in,
                              void* d_out, int out_size) {
    const float* data = (const float*)d_in[0];
    const float* rois = (const float*)d_in[1];
    const float* w1   = (const float*)d_in[2];
    const float* b1   = (const float*)d_in[3];
    const float* w2   = (const float*)d_in[4];
    const float* b2   = (const float*)d_in[5];
    const float* w3   = (const float*)d_in[6];
    const float* b3   = (const float*)d_in[7];
    const float* mw1  = (const float*)d_in[8];
    const float* mb1  = (const float*)d_in[9];
    const float* mw2  = (const float*)d_in[10];
    const float* mb2  = (const float*)d_in[11];
    float* out = (float*)d_out;

    float *xf, *h1, *m1, *h2, *off, *maskb, *w1p, *mw1p, *w2t;
    cudaGetSymbolAddress((void**)&xf,    g_xf);
    cudaGetSymbolAddress((void**)&h1,    g_h1);
    cudaGetSymbolAddress((void**)&m1,    g_m1);
    cudaGetSymbolAddress((void**)&h2,    g_h2);
    cudaGetSymbolAddress((void**)&off,   g_off);
    cudaGetSymbolAddress((void**)&maskb, g_mask);
    cudaGetSymbolAddress((void**)&w1p,   g_w1p);
    cudaGetSymbolAddress((void**)&mw1p,  g_mw1p);
    cudaGetSymbolAddress((void**)&w2t,   g_w2t);

    // 1. layout transform + weight prep
    k_transpose<<<dim3(4, 512, 8), dim3(32, 8)>>>(data);
    k_wprep<<<FIN, 256>>>(w1, mw1);
    k_w2cvt<<<FC, 256>>>(w2);

    // 2. pool pass 1 -> xf [n][bin*256+c] (tf32-rounded)
    k_pool<<<NROI * NBIN, 64>>>(rois, nullptr, nullptr, xf, 1);

    // 3. G1 fused: xf @ w1p -> h1 (relu) | xf @ mw1p -> m1 (relu)
    k_gemm_tf32<<<dim3(FC / 128, (NROI + 127) / 128, 2), 256>>>(
        xf, FIN, w1p, FC, b1, h1, FC, mw1p, mb1, m1,
        NROI, FC, FIN, 1, 1);

    // 4. G2: h1 @ w2t -> h2 (relu)
    k_gemm_tf32<<<dim3(FC / 128, (NROI + 127) / 128, 1), 256>>>(
        h1, FC, w2t, FC, b2, h2, FC, nullptr, nullptr, nullptr,
        NROI, FC, FC, 1, 0);

    // 5. G3: h2 @ w3 -> offsets [2000,98]
    k_head<<<NROI / 8, 256>>>(h2, w3, b3, off, 98, 0);

    // 6. G4: m1 @ mw2 -> mask [2000,49] (sigmoid)
    k_head<<<NROI / 8, 256>>>(m1, mw2, mb2, maskb, 49, 2);

    // 7. pool pass 2 (offset + mask) -> d_out [N,C,7,7]
    k_pool<<<NROI * NBIN, 64>>>(rois, off, maskb, out, 2);
}

// round 5
// speedup vs baseline: 2.5283x; 1.4419x over previous
#include <cuda_runtime.h>
#include <cuda_bf16.h>
#include <math.h>
#include <stdint.h>

#define OUTW 7
#define SPP 4
#define CCH 256
#define HH 128
#define WW 128
#define BB 4
#define NROI 2000
#define FIN (OUTW*OUTW*CCH)   /* 12544 */
#define FC 1024
#define NBIN (OUTW*OUTW)      /* 49 */

// ---------------- scratch (static device globals; no dynamic alloc) ----------
__device__ float          g_dataT[(size_t)BB*HH*WW*CCH];   // [B,H,W,C] 64 MB
__device__ __nv_bfloat16  g_xf[(size_t)NROI*FIN];          // pooled feats bf16
__device__ __nv_bfloat16  g_h1[(size_t)NROI*FC];
__device__ __nv_bfloat16  g_m1[(size_t)NROI*FC];
__device__ __nv_bfloat16  g_h2[(size_t)NROI*FC];
__device__ float          g_off[(size_t)NROI*2*NBIN];
__device__ float          g_mask[(size_t)NROI*NBIN];
__device__ uint32_t       g_w1p[(size_t)(FIN/2)*FC];       // permuted bf16x2 w1
__device__ uint32_t       g_mw1p[(size_t)(FIN/2)*FC];      // permuted bf16x2 mw1
__device__ uint32_t       g_w2p[(size_t)(FC/2)*FC];        // bf16x2 w2

// ---------------- helpers ------------------------------------------------------
__device__ __forceinline__ uint32_t packbf(float lo, float hi) {
    __nv_bfloat162 h = __floats2bfloat162_rn(lo, hi);
    return *(uint32_t*)&h;
}

__device__ __forceinline__ void mma_bf16(float* c, const uint32_t* a, const uint32_t* b) {
    asm volatile(
        "mma.sync.aligned.m16n8k16.row.col.f32.bf16.bf16.f32 "
        "{%0,%1,%2,%3}, {%4,%5,%6,%7}, {%8,%9}, {%0,%1,%2,%3};"
        : "+f"(c[0]), "+f"(c[1]), "+f"(c[2]), "+f"(c[3])
        : "r"(a[0]), "r"(a[1]), "r"(a[2]), "r"(a[3]), "r"(b[0]), "r"(b[1]));
}

__device__ __forceinline__ void cp_async16(uint32_t dst, const void* src, bool pred) {
    int sz = pred ? 16 : 0;
    asm volatile("cp.async.cg.shared.global [%0], [%1], 16, %2;\n"
                 :: "r"(dst), "l"(src), "r"(sz));
}
__device__ __forceinline__ void cp_commit() {
    asm volatile("cp.async.commit_group;\n" ::: "memory");
}
template <int N>
__device__ __forceinline__ void cp_wait() {
    asm volatile("cp.async.wait_group %0;\n" :: "n"(N) : "memory");
}

// ---------------- transpose [B,C,H,W] -> [B,H,W,C] ---------------------------
__global__ void k_transpose(const float* __restrict__ data) {
    __shared__ float tile[32][33];
    int xt = blockIdx.x;
    int by = blockIdx.y;
    int ct = blockIdx.z;
    int b = by >> 7, y = by & 127;
    int x0 = xt * 32, c0 = ct * 32;
    int tx = threadIdx.x, ty = threadIdx.y;
#pragma unroll
    for (int i = 0; i < 4; i++) {
        int c = c0 + ty + 8 * i;
        tile[ty + 8 * i][tx] =
            data[(((size_t)b * CCH + c) * HH + y) * WW + x0 + tx];
    }
    __syncthreads();
#pragma unroll
    for (int i = 0; i < 4; i++) {
        int x = x0 + ty + 8 * i;
        g_dataT[(((size_t)b * HH + y) * WW + x) * CCH + c0 + tx] =
            tile[tx][ty + 8 * i];
    }
}

// ---------------- weight prep: permute+pack w1/mw1 to bf16 pairs --------------
// dst pair-row kp covers permuted k rows (2kp, 2kp+1). permuted k = bin*256+c
// maps to source row c*49+bin; rows 2kp,2kp+1 share bin, c and c+1.
__global__ void k_wprep(const float* __restrict__ w1, const float* __restrict__ mw1) {
    int kp = blockIdx.x;                 // 0..6271
    int k0 = kp * 2;
    int c = k0 & 255, bin = k0 >> 8;
    size_t src0 = (size_t)(c * NBIN + bin) * FC;
    size_t src1 = src0 + (size_t)NBIN * FC;   // c+1, same bin
    int col = threadIdx.x * 4;
    size_t dst = (size_t)kp * FC + col;

    float4 a = *(const float4*)(w1 + src0 + col);
    float4 b = *(const float4*)(w1 + src1 + col);
    uint4 u = make_uint4(packbf(a.x, b.x), packbf(a.y, b.y),
                         packbf(a.z, b.z), packbf(a.w, b.w));
    *(uint4*)(g_w1p + dst) = u;

    a = *(const float4*)(mw1 + src0 + col);
    b = *(const float4*)(mw1 + src1 + col);
    u = make_uint4(packbf(a.x, b.x), packbf(a.y, b.y),
                   packbf(a.z, b.z), packbf(a.w, b.w));
    *(uint4*)(g_mw1p + dst) = u;
}

__global__ void k_w2prep(const float* __restrict__ w2) {
    int kp = blockIdx.x;                 // 0..511
    size_t src0 = (size_t)(kp * 2) * FC;
    size_t src1 = src0 + FC;
    int col = threadIdx.x * 4;
    float4 a = *(const float4*)(w2 + src0 + col);
    float4 b = *(const float4*)(w2 + src1 + col);
    uint4 u = make_uint4(packbf(a.x, b.x), packbf(a.y, b.y),
                         packbf(a.z, b.z), packbf(a.w, b.w));
    *(uint4*)(g_w2p + (size_t)kp * FC + col) = u;
}

// ---------------- deform ROI pool: per-cell weight factorization --------------
// One (roi,bin) per 64-thread block; thread = 4 channels (float4).
// pass 1: outh = xf bf16, layout [n][bin*256+c].
// pass 2: outf = d_out fp32, layout [n][c*49+bin], norm folds in mask.
__global__ void __launch_bounds__(64) k_pool(
        const float* __restrict__ rois,
        const float* __restrict__ offset,
        const float* __restrict__ mask,
        float* __restrict__ outf,
        __nv_bfloat16* __restrict__ outh,
        int pass) {
    int bidx = blockIdx.x;
    int n = bidx / NBIN;
    int bin = bidx % NBIN;
    int ph = bin / OUTW, pw = bin % OUTW;
    int tid = threadIdx.x;

    __shared__ float wcell[48];
    __shared__ float snorm;
    __shared__ int   sbase;
    __shared__ unsigned long long smask;

    if (tid < 48) wcell[tid] = 0.0f;
    __syncthreads();

    const float* r = rois + n * 5;
    if (tid < 16) {
        float sw = floorf(r[1] + 0.5f) * 0.0625f - 0.5f;
        float sh = floorf(r[2] + 0.5f) * 0.0625f - 0.5f;
        float ew = (floorf(r[3] + 0.5f) + 1.0f) * 0.0625f - 0.5f;
        float eh = (floorf(r[4] + 0.5f) + 1.0f) * 0.0625f - 0.5f;
        float rw = fmaxf(ew - sw, 0.1f);
        float rh = fmaxf(eh - sh, 0.1f);
        float bw = rw / 7.0f, bh = rh / 7.0f;
        float subw = bw / 4.0f, subh = bh / 4.0f;
        float ws0 = (float)pw * bw + sw;
        float hs0 = (float)ph * bh + sh;
        if (pass == 2) {
            ws0 += offset[(size_t)n * 98 + bin] * 0.1f * rw;
            hs0 += offset[(size_t)n * 98 + 49 + bin] * 0.1f * rh;
        }
        int ix = tid & 3, iy = tid >> 2;
        float w = ws0 + (float)ix * subw;
        float h = hs0 + (float)iy * subh;
        bool valid = (w >= -0.5f) && (w <= (float)WW - 0.5f) &&
                     (h >= -0.5f) && (h <= (float)HH - 0.5f);
        float wc = fminf(fmaxf(w, 0.0f), (float)(WW - 1));
        float hc = fminf(fmaxf(h, 0.0f), (float)(HH - 1));
        int x0 = (int)floorf(wc);
        int y0 = (int)floorf(hc);
        int x1 = min(x0 + 1, WW - 1);
        int y1 = min(y0 + 1, HH - 1);
        int gx = x0, gy = y0;
#pragma unroll
        for (int o = 8; o >= 1; o >>= 1) {
            gx = min(gx, __shfl_xor_sync(0xFFFFu, gx, o));
            gy = min(gy, __shfl_xor_sync(0xFFFFu, gy, o));
        }
        float dx = wc - (float)x0;
        float dy = hc - (float)y0;
        int c00 = ((y0 - gy) << 3) + (x0 - gx);
        int c01 = ((y0 - gy) << 3) + (x1 - gx);
        int c10 = ((y1 - gy) << 3) + (x0 - gx);
        int c11 = ((y1 - gy) << 3) + (x1 - gx);
        unsigned long long m = 0ull;
        float cnt = valid ? 1.0f : 0.0f;
        if (valid) {
            atomicAdd(&wcell[c00], (1.0f - dx) * (1.0f - dy));
            atomicAdd(&wcell[c01], dx * (1.0f - dy));
            atomicAdd(&wcell[c10], (1.0f - dx) * dy);
            atomicAdd(&wcell[c11], dx * dy);
            m = (1ull << c00) | (1ull << c01) | (1ull << c10) | (1ull << c11);
        }
#pragma unroll
        for (int o = 8; o >= 1; o >>= 1) {
            m |= __shfl_xor_sync(0xFFFFu, m, o);
            cnt += __shfl_xor_sync(0xFFFFu, cnt, o);
        }
        if (tid == 0) {
            smask = m;
            int b = (int)r[0];
            sbase = b * (HH * WW * 64) + (gy * WW + gx) * 64;  // float4 units
            float norm = (cnt > 0.0f) ? 1.0f / cnt : 0.0f;
            if (pass == 2) norm *= mask[(size_t)n * NBIN + bin];
            snorm = norm;
        }
    }
    __syncthreads();

    unsigned long long m = smask;
    float norm = snorm;
    const float4* base = (const float4*)g_dataT;
    int baseIdx = sbase + tid;

    float ax = 0.f, ay = 0.f, az = 0.f, aw = 0.f;
    while (m) {
        int cell = __ffsll((long long)m) - 1;
        m &= m - 1;
        float w = wcell[cell];
        int idx = baseIdx + (cell >> 3) * (WW * 64) + (cell & 7) * 64;
        float4 v = base[idx];
        ax += w * v.x; ay += w * v.y; az += w * v.z; aw += w * v.w;
    }
    ax *= norm; ay *= norm; az *= norm; aw *= norm;

    if (pass == 2) {
        float* o = outf + (size_t)n * FIN + (size_t)(tid * 4) * NBIN + bin;
        o[0]        = ax;
        o[NBIN]     = ay;
        o[2 * NBIN] = az;
        o[3 * NBIN] = aw;
    } else {
        uint2 v = make_uint2(packbf(ax, ay), packbf(az, aw));
        *(uint2*)(outh + (size_t)n * FIN + (size_t)bin * 256 + tid * 4) = v;
    }
}

// ---------------- bf16 tensor-core GEMM (cp.async double-buffered) ------------
// A [M,K] bf16 row-major (lda in elems). B pair-packed u32 [K/2][N].
// C bf16 [M,ldc]. K%32==0, N%128==0. gridDim.z==2 selects second head.
#define LDA_S 20    /* u32 pairs per A smem row (16 used) */
#define LDB_S 136   /* u32 per B smem kp row (128 used)   */
__global__ void __launch_bounds__(256, 2) k_gemm_bf16(
    const __nv_bfloat16* __restrict__ A, int lda,
    const uint32_t* __restrict__ B,
    const float* __restrict__ bias,
    __nv_bfloat16* __restrict__ C, int ldc,
    const uint32_t* __restrict__ B2,
    const float* __restrict__ bias2,
    __nv_bfloat16* __restrict__ C2,
    int M, int N, int K, int act) {
    if (blockIdx.z == 1) { B = B2; bias = bias2; C = C2; }

    __shared__ uint32_t As[2][128 * LDA_S];
    __shared__ uint32_t Bs[2][16 * LDB_S];

    int tid = threadIdx.x;
    int warp = tid >> 5, lane = tid & 31;
    int g = lane >> 2, t = lane & 3;
    int wm = warp >> 2;
    int wn = warp & 3;
    int bm = blockIdx.y * 128, bn = blockIdx.x * 128;

    int arow = tid >> 2;              // 0..63
    int akc  = (tid & 3) * 4;         // pair offset 0,4,8,12
    int bkr  = tid >> 5;              // kp row 0..7
    int bn4  = lane * 4;              // u32 col

    const __nv_bfloat16* Ap0 = A + (size_t)(bm + arow) * lda + akc * 2;
    const __nv_bfloat16* Ap1 = A + (size_t)(bm + arow + 64) * lda + akc * 2;
    bool am0 = (bm + arow) < M;
    bool am1 = (bm + arow + 64) < M;
    const uint32_t* Bp0 = B + (size_t)bkr * N + bn + bn4;
    const uint32_t* Bp1 = B + (size_t)(bkr + 8) * N + bn + bn4;

    uint32_t sa0[2], sa1[2], sb0[2], sb1[2];
#pragma unroll
    for (int s = 0; s < 2; s++) {
        sa0[s] = (uint32_t)__cvta_generic_to_shared(&As[s][arow * LDA_S + akc]);
        sa1[s] = (uint32_t)__cvta_generic_to_shared(&As[s][(arow + 64) * LDA_S + akc]);
        sb0[s] = (uint32_t)__cvta_generic_to_shared(&Bs[s][bkr * LDB_S + bn4]);
        sb1[s] = (uint32_t)__cvta_generic_to_shared(&Bs[s][(bkr + 8) * LDB_S + bn4]);
    }

    float acc[4][4][4];
#pragma unroll
    for (int i = 0; i < 4; i++)
#pragma unroll
        for (int j = 0; j < 4; j++)
#pragma unroll
            for (int q = 0; q < 4; q++) acc[i][j][q] = 0.0f;

    int nt = K / 32;                  // 32 bf16 (16 pairs) per outer tile
    cp_async16(sa0[0], Ap0, am0);
    cp_async16(sa1[0], Ap1, am1);
    cp_async16(sb0[0], Bp0, true);
    cp_async16(sb1[0], Bp1, true);
    cp_commit();

    for (int kt = 0; kt < nt; kt++) {
        int cur = kt & 1;
        if (kt + 1 < nt) {
            int ke = (kt + 1) * 32;          // bf16 elems
            int kp = (kt + 1) * 16;          // pair rows for B
            cp_async16(sa0[cur ^ 1], Ap0 + ke, am0);
            cp_async16(sa1[cur ^ 1], Ap1 + ke, am1);
            cp_async16(sb0[cur ^ 1], Bp0 + (size_t)kp * N, true);
            cp_async16(sb1[cur ^ 1], Bp1 + (size_t)kp * N, true);
            cp_commit();
            cp_wait<1>();
        } else {
            cp_wait<0>();
        }
        __syncthreads();

        const uint32_t* Au = As[cur];
        const uint32_t* Bu = Bs[cur];
#pragma unroll
        for (int ko = 0; ko < 2; ko++) {
            int kb = ko * 8;                 // pair units
            uint32_t af[4][4], bf[4][2];
#pragma unroll
            for (int i = 0; i < 4; i++) {
                int m0 = wm * 64 + i * 16;
                af[i][0] = Au[(m0 + g) * LDA_S + kb + t];
                af[i][1] = Au[(m0 + g + 8) * LDA_S + kb + t];
                af[i][2] = Au[(m0 + g) * LDA_S + kb + t + 4];
                af[i][3] = Au[(m0 + g + 8) * LDA_S + kb + t + 4];
            }
#pragma unroll
            for (int j = 0; j < 4; j++) {
                int n0 = wn * 32 + j * 8;
                bf[j][0] = Bu[(kb + t) * LDB_S + n0 + g];
                bf[j][1] = Bu[(kb + t + 4) * LDB_S + n0 + g];
            }
#pragma unroll
            for (int i = 0; i < 4; i++)
#pragma unroll
                for (int j = 0; j < 4; j++)
                    mma_bf16(acc[i][j], af[i], bf[j]);
        }
        __syncthreads();
    }

    // epilogue: bias + act, store bf16 pairs
#pragma unroll
    for (int i = 0; i < 4; i++) {
        int r0 = bm + wm * 64 + i * 16 + g;
        int r1 = r0 + 8;
#pragma unroll
        for (int j = 0; j < 4; j++) {
            int c0 = bn + wn * 32 + j * 8 + 2 * t;
            float bv0 = bias[c0], bv1 = bias[c0 + 1];
            float vv[4] = {acc[i][j][0] + bv0, acc[i][j][1] + bv1,
                           acc[i][j][2] + bv0, acc[i][j][3] + bv1};
#pragma unroll
            for (int q = 0; q < 4; q++) {
                if (act == 1) vv[q] = fmaxf(vv[q], 0.0f);
                else if (act == 2) vv[q] = 1.0f / (1.0f + expf(-vv[q]));
            }
            if (r0 < M)
                *(uint32_t*)(C + (size_t)r0 * ldc + c0) = packbf(vv[0], vv[1]);
            if (r1 < M)
                *(uint32_t*)(C + (size_t)r1 * ldc + c0) = packbf(vv[2], vv[3]);
        }
    }
}

// ---------------- small-N head GEMM (A bf16, B/bias fp32) ---------------------
__global__ void __launch_bounds__(256) k_head(
        const __nv_bfloat16* __restrict__ A, const float* __restrict__ B,
        const float* __restrict__ bias, float* __restrict__ C,
        int N, int act) {
    __shared__ float Asm[8 * FC];
    int tid = threadIdx.x;
    int m0 = blockIdx.x * 8;
    const uint4* Af = (const uint4*)(A + (size_t)m0 * FC);  // 8 bf16 per uint4
#pragma unroll
    for (int i = 0; i < 4; i++) {
        int idx = tid + 256 * i;            // 1024 uint4 total
        uint4 u = Af[idx];
        float2 f0 = __bfloat1622float2(*(__nv_bfloat162*)&u.x);
        float2 f1 = __bfloat1622float2(*(__nv_bfloat162*)&u.y);
        float2 f2 = __bfloat1622float2(*(__nv_bfloat162*)&u.z);
        float2 f3 = __bfloat1622float2(*(__nv_bfloat162*)&u.w);
        float* d = Asm + idx * 8;
        d[0] = f0.x; d[1] = f0.y; d[2] = f1.x; d[3] = f1.y;
        d[4] = f2.x; d[5] = f2.y; d[6] = f3.x; d[7] = f3.y;
    }
    __syncthreads();

    int row = tid >> 5, lane = tid & 31;
    float acc[4] = {0.f, 0.f, 0.f, 0.f};
    const float* ar = Asm + row * FC;
    for (int k = 0; k < FC; k += 2) {
        float a0 = ar[k], a1 = ar[k + 1];
        const float* bk0 = B + (size_t)k * N;
        const float* bk1 = bk0 + N;
#pragma unroll
        for (int j = 0; j < 4; j++) {
            int col = lane + 32 * j;
            if (col < N) {
                acc[j] += a0 * bk0[col];
                acc[j] += a1 * bk1[col];
            }
        }
    }
#pragma unroll
    for (int j = 0; j < 4; j++) {
        int col = lane + 32 * j;
        if (col < N) {
            float v = acc[j] + bias[col];
            if (act == 1) v = fmaxf(v, 0.0f);
            else if (act == 2) v = 1.0f / (1.0f + expf(-v));
            C[(size_t)(m0 + row) * N + col] = v;
        }
    }
}

// ---------------- launch ------------------------------------------------------
extern "C" void kernel_launch(void* const* d_in, const int* in_sizes, int n_in,
                              void* d_out, int out_size) {
    const float* data = (const float*)d_in[0];
    const float* rois = (const float*)d_in[1];
    const float* w1   = (const float*)d_in[2];
    const float* b1   = (const float*)d_in[3];
    const float* w2   = (const float*)d_in[4];
    const float* b2   = (const float*)d_in[5];
    const float* w3   = (const float*)d_in[6];
    const float* b3   = (const float*)d_in[7];
    const float* mw1  = (const float*)d_in[8];
    const float* mb1  = (const float*)d_in[9];
    const float* mw2  = (const float*)d_in[10];
    const float* mb2  = (const float*)d_in[11];
    float* out = (float*)d_out;

    __nv_bfloat16 *xf, *h1, *m1, *h2;
    float *off, *maskb;
    uint32_t *w1p, *mw1p, *w2p;
    cudaGetSymbolAddress((void**)&xf,    g_xf);
    cudaGetSymbolAddress((void**)&h1,    g_h1);
    cudaGetSymbolAddress((void**)&m1,    g_m1);
    cudaGetSymbolAddress((void**)&h2,    g_h2);
    cudaGetSymbolAddress((void**)&off,   g_off);
    cudaGetSymbolAddress((void**)&maskb, g_mask);
    cudaGetSymbolAddress((void**)&w1p,   g_w1p);
    cudaGetSymbolAddress((void**)&mw1p,  g_mw1p);
    cudaGetSymbolAddress((void**)&w2p,   g_w2p);

    // 1. layout transform + weight prep (pack bf16 pairs)
    k_transpose<<<dim3(4, 512, 8), dim3(32, 8)>>>(data);
    k_wprep<<<FIN / 2, 256>>>(w1, mw1);
    k_w2prep<<<FC / 2, 256>>>(w2);

    // 2. pool pass 1 -> xf bf16 [n][bin*256+c]
    k_pool<<<NROI * NBIN, 64>>>(rois, nullptr, nullptr, nullptr, xf, 1);

    // 3. G1 fused: xf @ w1 -> h1 (relu) | xf @ mw1 -> m1 (relu)   [bf16 TC]
    k_gemm_bf16<<<dim3(FC / 128, (NROI + 127) / 128, 2), 256>>>(
        xf, FIN, w1p, b1, h1, FC, mw1p, mb1, m1,
        NROI, FC, FIN, 1);

    // 4. G2: h1 @ w2 -> h2 (relu)   [bf16 TC]
    k_gemm_bf16<<<dim3(FC / 128, (NROI + 127) / 128, 1), 256>>>(
        h1, FC, w2p, b2, h2, FC, nullptr, nullptr, nullptr,
        NROI, FC, FC, 1);

    // 5. G3: h2 @ w3 -> offsets [2000,98]
    k_head<<<NROI / 8, 256>>>(h2, w3, b3, off, 98, 0);

    // 6. G4: m1 @ mw2 -> mask [2000,49] (sigmoid)
    k_head<<<NROI / 8, 256>>>(m1, mw2, mb2, maskb, 49, 2);

    // 7. pool pass 2 (offset + mask) -> d_out [N,C,7,7]
    k_pool<<<NROI * NBIN, 64>>>(rois, off, maskb, out, nullptr, 2);
}

// round 7
// speedup vs baseline: 2.6120x; 1.0331x over previous
#include <cuda_runtime.h>
#include <cuda_bf16.h>
#include <math.h>
#include <stdint.h>

#define OUTW 7
#define SPP 4
#define CCH 256
#define HH 128
#define WW 128
#define BB 4
#define NROI 2000
#define FIN (OUTW*OUTW*CCH)   /* 12544 */
#define FC 1024
#define NBIN (OUTW*OUTW)      /* 49 */

// ---------------- scratch (static device globals; no dynamic alloc) ----------
__device__ float          g_dataT[(size_t)BB*HH*WW*CCH];   // [B,H,W,C] 64 MB
__device__ __nv_bfloat16  g_xf[(size_t)NROI*FIN];          // pooled feats bf16
__device__ __nv_bfloat16  g_h1[(size_t)NROI*FC];
__device__ __nv_bfloat16  g_m1[(size_t)NROI*FC];
__device__ __nv_bfloat16  g_h2[(size_t)NROI*FC];
__device__ float          g_off[(size_t)NROI*2*NBIN];
__device__ float          g_mask[(size_t)NROI*NBIN];
__device__ uint32_t       g_w1p[(size_t)(FIN/2)*FC];       // permuted bf16x2 w1
__device__ uint32_t       g_mw1p[(size_t)(FIN/2)*FC];      // permuted bf16x2 mw1
__device__ uint32_t       g_w2p[(size_t)(FC/2)*FC];        // bf16x2 w2

// ---------------- helpers ------------------------------------------------------
__device__ __forceinline__ uint32_t packbf(float lo, float hi) {
    __nv_bfloat162 h = __floats2bfloat162_rn(lo, hi);
    return *(uint32_t*)&h;
}

__device__ __forceinline__ void mma_bf16(float* c, const uint32_t* a, const uint32_t* b) {
    asm volatile(
        "mma.sync.aligned.m16n8k16.row.col.f32.bf16.bf16.f32 "
        "{%0,%1,%2,%3}, {%4,%5,%6,%7}, {%8,%9}, {%0,%1,%2,%3};"
        : "+f"(c[0]), "+f"(c[1]), "+f"(c[2]), "+f"(c[3])
        : "r"(a[0]), "r"(a[1]), "r"(a[2]), "r"(a[3]), "r"(b[0]), "r"(b[1]));
}

__device__ __forceinline__ void cp_async16(uint32_t dst, const void* src, bool pred) {
    int sz = pred ? 16 : 0;
    asm volatile("cp.async.cg.shared.global [%0], [%1], 16, %2;\n"
                 :: "r"(dst), "l"(src), "r"(sz));
}
__device__ __forceinline__ void cp_commit() {
    asm volatile("cp.async.commit_group;\n" ::: "memory");
}
template <int N>
__device__ __forceinline__ void cp_wait() {
    asm volatile("cp.async.wait_group %0;\n" :: "n"(N) : "memory");
}

// ---------------- transpose [B,C,H,W] -> [B,H,W,C] ---------------------------
__global__ void k_transpose(const float* __restrict__ data) {
    __shared__ float tile[32][33];
    int xt = blockIdx.x;
    int by = blockIdx.y;
    int ct = blockIdx.z;
    int b = by >> 7, y = by & 127;
    int x0 = xt * 32, c0 = ct * 32;
    int tx = threadIdx.x, ty = threadIdx.y;
#pragma unroll
    for (int i = 0; i < 4; i++) {
        int c = c0 + ty + 8 * i;
        tile[ty + 8 * i][tx] =
            data[(((size_t)b * CCH + c) * HH + y) * WW + x0 + tx];
    }
    __syncthreads();
#pragma unroll
    for (int i = 0; i < 4; i++) {
        int x = x0 + ty + 8 * i;
        g_dataT[(((size_t)b * HH + y) * WW + x) * CCH + c0 + tx] =
            tile[tx][ty + 8 * i];
    }
}

// ---------------- weight prep: permute+pack w1/mw1 to bf16 pairs --------------
__global__ void k_wprep(const float* __restrict__ w1, const float* __restrict__ mw1) {
    int kp = blockIdx.x;                 // 0..6271
    int k0 = kp * 2;
    int c = k0 & 255, bin = k0 >> 8;
    size_t src0 = (size_t)(c * NBIN + bin) * FC;
    size_t src1 = src0 + (size_t)NBIN * FC;   // c+1, same bin
    int col = threadIdx.x * 4;
    size_t dst = (size_t)kp * FC + col;

    float4 a = *(const float4*)(w1 + src0 + col);
    float4 b = *(const float4*)(w1 + src1 + col);
    uint4 u = make_uint4(packbf(a.x, b.x), packbf(a.y, b.y),
                         packbf(a.z, b.z), packbf(a.w, b.w));
    *(uint4*)(g_w1p + dst) = u;

    a = *(const float4*)(mw1 + src0 + col);
    b = *(const float4*)(mw1 + src1 + col);
    u = make_uint4(packbf(a.x, b.x), packbf(a.y, b.y),
                   packbf(a.z, b.z), packbf(a.w, b.w));
    *(uint4*)(g_mw1p + dst) = u;
}

__global__ void k_w2prep(const float* __restrict__ w2) {
    int kp = blockIdx.x;                 // 0..511
    size_t src0 = (size_t)(kp * 2) * FC;
    size_t src1 = src0 + FC;
    int col = threadIdx.x * 4;
    float4 a = *(const float4*)(w2 + src0 + col);
    float4 b = *(const float4*)(w2 + src1 + col);
    uint4 u = make_uint4(packbf(a.x, b.x), packbf(a.y, b.y),
                         packbf(a.z, b.z), packbf(a.w, b.w));
    *(uint4*)(g_w2p + (size_t)kp * FC + col) = u;
}

// ---------------- deform ROI pool: per-cell weight factorization --------------
__global__ void __launch_bounds__(64) k_pool(
        const float* __restrict__ rois,
        const float* __restrict__ offset,
        const float* __restrict__ mask,
        float* __restrict__ outf,
        __nv_bfloat16* __restrict__ outh,
        int pass) {
    int bidx = blockIdx.x;
    int n = bidx / NBIN;
    int bin = bidx % NBIN;
    int ph = bin / OUTW, pw = bin % OUTW;
    int tid = threadIdx.x;

    __shared__ float wcell[48];
    __shared__ float snorm;
    __shared__ int   sbase;
    __shared__ unsigned long long smask;

    if (tid < 48) wcell[tid] = 0.0f;
    __syncthreads();

    const float* r = rois + n * 5;
    if (tid < 16) {
        float sw = floorf(r[1] + 0.5f) * 0.0625f - 0.5f;
        float sh = floorf(r[2] + 0.5f) * 0.0625f - 0.5f;
        float ew = (floorf(r[3] + 0.5f) + 1.0f) * 0.0625f - 0.5f;
        float eh = (floorf(r[4] + 0.5f) + 1.0f) * 0.0625f - 0.5f;
        float rw = fmaxf(ew - sw, 0.1f);
        float rh = fmaxf(eh - sh, 0.1f);
        float bw = rw / 7.0f, bh = rh / 7.0f;
        float subw = bw / 4.0f, subh = bh / 4.0f;
        float ws0 = (float)pw * bw + sw;
        float hs0 = (float)ph * bh + sh;
        if (pass == 2) {
            ws0 += offset[(size_t)n * 98 + bin] * 0.1f * rw;
            hs0 += offset[(size_t)n * 98 + 49 + bin] * 0.1f * rh;
        }
        int ix = tid & 3, iy = tid >> 2;
        float w = ws0 + (float)ix * subw;
        float h = hs0 + (float)iy * subh;
        bool valid = (w >= -0.5f) && (w <= (float)WW - 0.5f) &&
                     (h >= -0.5f) && (h <= (float)HH - 0.5f);
        float wc = fminf(fmaxf(w, 0.0f), (float)(WW - 1));
        float hc = fminf(fmaxf(h, 0.0f), (float)(HH - 1));
        int x0 = (int)floorf(wc);
        int y0 = (int)floorf(hc);
        int x1 = min(x0 + 1, WW - 1);
        int y1 = min(y0 + 1, HH - 1);
        int gx = x0, gy = y0;
#pragma unroll
        for (int o = 8; o >= 1; o >>= 1) {
            gx = min(gx, __shfl_xor_sync(0xFFFFu, gx, o));
            gy = min(gy, __shfl_xor_sync(0xFFFFu, gy, o));
        }
        float dx = wc - (float)x0;
        float dy = hc - (float)y0;
        int c00 = ((y0 - gy) << 3) + (x0 - gx);
        int c01 = ((y0 - gy) << 3) + (x1 - gx);
        int c10 = ((y1 - gy) << 3) + (x0 - gx);
        int c11 = ((y1 - gy) << 3) + (x1 - gx);
        unsigned long long m = 0ull;
        float cnt = valid ? 1.0f : 0.0f;
        if (valid) {
            atomicAdd(&wcell[c00], (1.0f - dx) * (1.0f - dy));
            atomicAdd(&wcell[c01], dx * (1.0f - dy));
            atomicAdd(&wcell[c10], (1.0f - dx) * dy);
            atomicAdd(&wcell[c11], dx * dy);
            m = (1ull << c00) | (1ull << c01) | (1ull << c10) | (1ull << c11);
        }
#pragma unroll
        for (int o = 8; o >= 1; o >>= 1) {
            m |= __shfl_xor_sync(0xFFFFu, m, o);
            cnt += __shfl_xor_sync(0xFFFFu, cnt, o);
        }
        if (tid == 0) {
            smask = m;
            int b = (int)r[0];
            sbase = b * (HH * WW * 64) + (gy * WW + gx) * 64;  // float4 units
            float norm = (cnt > 0.0f) ? 1.0f / cnt : 0.0f;
            if (pass == 2) norm *= mask[(size_t)n * NBIN + bin];
            snorm = norm;
        }
    }
    __syncthreads();

    unsigned long long m = smask;
    float norm = snorm;
    const float4* base = (const float4*)g_dataT;
    int baseIdx = sbase + tid;

    float ax = 0.f, ay = 0.f, az = 0.f, aw = 0.f;
    while (m) {
        int cell = __ffsll((long long)m) - 1;
        m &= m - 1;
        float w = wcell[cell];
        int idx = baseIdx + (cell >> 3) * (WW * 64) + (cell & 7) * 64;
        float4 v = base[idx];
        ax += w * v.x; ay += w * v.y; az += w * v.z; aw += w * v.w;
    }
    ax *= norm; ay *= norm; az *= norm; aw *= norm;

    if (pass == 2) {
        float* o = outf + (size_t)n * FIN + (size_t)(tid * 4) * NBIN + bin;
        o[0]        = ax;
        o[NBIN]     = ay;
        o[2 * NBIN] = az;
        o[3 * NBIN] = aw;
    } else {
        uint2 v = make_uint2(packbf(ax, ay), packbf(az, aw));
        *(uint2*)(outh + (size_t)n * FIN + (size_t)bin * 256 + tid * 4) = v;
    }
}

// ---------------- bf16 tensor-core GEMM (4-stage cp.async pipeline) -----------
// A [M,K] bf16 row-major (lda in elems). B pair-packed u32 [K/2][N].
// C bf16 [M,ldc]. K%32==0, N%128==0. gridDim.z==2 selects second head.
#define LDA_S 20    /* u32 pairs per A smem row (16 used) */
#define LDB_S 136   /* u32 per B smem kp row (128 used)   */
#define STAGES 4
#define A_ST (128 * LDA_S)
#define B_ST (16 * LDB_S)
#define GEMM_SMEM ((STAGES * (A_ST + B_ST)) * 4)

__global__ void __launch_bounds__(256, 2) k_gemm_bf16(
    const __nv_bfloat16* __restrict__ A, int lda,
    const uint32_t* __restrict__ B,
    const float* __restrict__ bias,
    __nv_bfloat16* __restrict__ C, int ldc,
    const uint32_t* __restrict__ B2,
    const float* __restrict__ bias2,
    __nv_bfloat16* __restrict__ C2,
    int M, int N, int K, int act) {
    if (blockIdx.z == 1) { B = B2; bias = bias2; C = C2; }

    extern __shared__ uint32_t sm[];
    uint32_t* Asm = sm;                       // STAGES * A_ST
    uint32_t* Bsm = sm + STAGES * A_ST;       // STAGES * B_ST

    int tid = threadIdx.x;
    int warp = tid >> 5, lane = tid & 31;
    int g = lane >> 2, t = lane & 3;
    int wm = warp >> 2;
    int wn = warp & 3;
    int bm = blockIdx.y * 128, bn = blockIdx.x * 128;

    int arow = tid >> 2;              // 0..63
    int akc  = (tid & 3) * 4;         // pair offset 0,4,8,12
    int bkr  = tid >> 5;              // kp row 0..7
    int bn4  = lane * 4;              // u32 col

    const __nv_bfloat16* Ap0 = A + (size_t)(bm + arow) * lda + akc * 2;
    const __nv_bfloat16* Ap1 = A + (size_t)(bm + arow + 64) * lda + akc * 2;
    bool am0 = (bm + arow) < M;
    bool am1 = (bm + arow + 64) < M;
    const uint32_t* Bp0 = B + (size_t)bkr * N + bn + bn4;
    const uint32_t* Bp1 = B + (size_t)(bkr + 8) * N + bn + bn4;

    uint32_t a_smem = (uint32_t)__cvta_generic_to_shared(Asm);
    uint32_t b_smem = (uint32_t)__cvta_generic_to_shared(Bsm);
    uint32_t da0 = a_smem + (uint32_t)(arow * LDA_S + akc) * 4;
    uint32_t da1 = a_smem + (uint32_t)((arow + 64) * LDA_S + akc) * 4;
    uint32_t db0 = b_smem + (uint32_t)(bkr * LDB_S + bn4) * 4;
    uint32_t db1 = b_smem + (uint32_t)((bkr + 8) * LDB_S + bn4) * 4;

    float acc[4][4][4];
#pragma unroll
    for (int i = 0; i < 4; i++)
#pragma unroll
        for (int j = 0; j < 4; j++)
#pragma unroll
            for (int q = 0; q < 4; q++) acc[i][j][q] = 0.0f;

    int nt = K / 32;

#define LOAD_STAGE(kt, s)                                                      \
    {                                                                          \
        int ke = (kt) * 32;                                                    \
        int kp = (kt) * 16;                                                    \
        uint32_t ao = (uint32_t)(s) * A_ST * 4;                                \
        uint32_t bo = (uint32_t)(s) * B_ST * 4;                                \
        cp_async16(da0 + ao, Ap0 + ke, am0);                                   \
        cp_async16(da1 + ao, Ap1 + ke, am1);                                   \
        cp_async16(db0 + bo, Bp0 + (size_t)kp * N, true);                      \
        cp_async16(db1 + bo, Bp1 + (size_t)kp * N, true);                      \
        cp_commit();                                                           \
    }

    // prologue: stages 0..2
    LOAD_STAGE(0, 0);
    LOAD_STAGE(1, 1);
    LOAD_STAGE(2, 2);

    for (int kt = 0; kt < nt; kt++) {
        cp_wait<STAGES - 2>();
        __syncthreads();
        if (kt + 3 < nt) {
            LOAD_STAGE(kt + 3, (kt + 3) & 3);
        } else {
            cp_commit();            // keep group counting uniform
        }

        int cur = kt & 3;
        const uint32_t* Au = Asm + cur * A_ST;
        const uint32_t* Bu = Bsm + cur * B_ST;

        uint32_t af[2][4][4], bf[2][4][2];
        // frags for ko=0
#pragma unroll
        for (int i = 0; i < 4; i++) {
            int m0 = wm * 64 + i * 16;
            af[0][i][0] = Au[(m0 + g) * LDA_S + t];
            af[0][i][1] = Au[(m0 + g + 8) * LDA_S + t];
            af[0][i][2] = Au[(m0 + g) * LDA_S + t + 4];
            af[0][i][3] = Au[(m0 + g + 8) * LDA_S + t + 4];
        }
#pragma unroll
        for (int j = 0; j < 4; j++) {
            int n0 = wn * 32 + j * 8;
            bf[0][j][0] = Bu[(t) * LDB_S + n0 + g];
            bf[0][j][1] = Bu[(t + 4) * LDB_S + n0 + g];
        }
        // prefetch frags for ko=1
#pragma unroll
        for (int i = 0; i < 4; i++) {
            int m0 = wm * 64 + i * 16;
            af[1][i][0] = Au[(m0 + g) * LDA_S + 8 + t];
            af[1][i][1] = Au[(m0 + g + 8) * LDA_S + 8 + t];
            af[1][i][2] = Au[(m0 + g) * LDA_S + 8 + t + 4];
            af[1][i][3] = Au[(m0 + g + 8) * LDA_S + 8 + t + 4];
        }
#pragma unroll
        for (int j = 0; j < 4; j++) {
            int n0 = wn * 32 + j * 8;
            bf[1][j][0] = Bu[(8 + t) * LDB_S + n0 + g];
            bf[1][j][1] = Bu[(8 + t + 4) * LDB_S + n0 + g];
        }
        // mma for both ko
#pragma unroll
        for (int ko = 0; ko < 2; ko++)
#pragma unroll
            for (int i = 0; i < 4; i++)
#pragma unroll
                for (int j = 0; j < 4; j++)
                    mma_bf16(acc[i][j], af[ko][i], bf[ko][j]);
        __syncthreads();
    }
    cp_wait<0>();

    // epilogue: bias + act, store bf16 pairs
#pragma unroll
    for (int i = 0; i < 4; i++) {
        int r0 = bm + wm * 64 + i * 16 + g;
        int r1 = r0 + 8;
#pragma unroll
        for (int j = 0; j < 4; j++) {
            int c0 = bn + wn * 32 + j * 8 + 2 * t;
            float bv0 = bias[c0], bv1 = bias[c0 + 1];
            float vv[4] = {acc[i][j][0] + bv0, acc[i][j][1] + bv1,
                           acc[i][j][2] + bv0, acc[i][j][3] + bv1};
#pragma unroll
            for (int q = 0; q < 4; q++) {
                if (act == 1) vv[q] = fmaxf(vv[q], 0.0f);
                else if (act == 2) vv[q] = 1.0f / (1.0f + expf(-vv[q]));
            }
            if (r0 < M)
                *(uint32_t*)(C + (size_t)r0 * ldc + c0) = packbf(vv[0], vv[1]);
            if (r1 < M)
                *(uint32_t*)(C + (size_t)r1 * ldc + c0) = packbf(vv[2], vv[3]);
        }
    }
#undef LOAD_STAGE
}

// ---------------- small-N head GEMM (A bf16, B/bias fp32) ---------------------
__global__ void __launch_bounds__(256) k_head(
        const __nv_bfloat16* __restrict__ A, const float* __restrict__ B,
        const float* __restrict__ bias, float* __restrict__ C,
        int N, int act) {
    __shared__ float Asm[8 * FC];
    int tid = threadIdx.x;
    int m0 = blockIdx.x * 8;
    const uint4* Af = (const uint4*)(A + (size_t)m0 * FC);  // 8 bf16 per uint4
#pragma unroll
    for (int i = 0; i < 4; i++) {
        int idx = tid + 256 * i;            // 1024 uint4 total
        uint4 u = Af[idx];
        float2 f0 = __bfloat1622float2(*(__nv_bfloat162*)&u.x);
        float2 f1 = __bfloat1622float2(*(__nv_bfloat162*)&u.y);
        float2 f2 = __bfloat1622float2(*(__nv_bfloat162*)&u.z);
        float2 f3 = __bfloat1622float2(*(__nv_bfloat162*)&u.w);
        float* d = Asm + idx * 8;
        d[0] = f0.x; d[1] = f0.y; d[2] = f1.x; d[3] = f1.y;
        d[4] = f2.x; d[5] = f2.y; d[6] = f3.x; d[7] = f3.y;
    }
    __syncthreads();

    int row = tid >> 5, lane = tid & 31;
    float acc[4] = {0.f, 0.f, 0.f, 0.f};
    const float* ar = Asm + row * FC;
    for (int k = 0; k < FC; k += 2) {
        float a0 = ar[k], a1 = ar[k + 1];
        const float* bk0 = B + (size_t)k * N;
        const float* bk1 = bk0 + N;
#pragma unroll
        for (int j = 0; j < 4; j++) {
            int col = lane + 32 * j;
            if (col < N) {
                acc[j] += a0 * bk0[col];
                acc[j] += a1 * bk1[col];
            }
        }
    }
#pragma unroll
    for (int j = 0; j < 4; j++) {
        int col = lane + 32 * j;
        if (col < N) {
            float v = acc[j] + bias[col];
            if (act == 1) v = fmaxf(v, 0.0f);
            else if (act == 2) v = 1.0f / (1.0f + expf(-v));
            C[(size_t)(m0 + row) * N + col] = v;
        }
    }
}

// ---------------- launch ------------------------------------------------------
extern "C" void kernel_launch(void* const* d_in, const int* in_sizes, int n_in,
                              void* d_out, int out_size) {
    const float* data = (const float*)d_in[0];
    const float* rois = (const float*)d_in[1];
    const float* w1   = (const float*)d_in[2];
    const float* b1   = (const float*)d_in[3];
    const float* w2   = (const float*)d_in[4];
    const float* b2   = (const float*)d_in[5];
    const float* w3   = (const float*)d_in[6];
    const float* b3   = (const float*)d_in[7];
    const float* mw1  = (const float*)d_in[8];
    const float* mb1  = (const float*)d_in[9];
    const float* mw2  = (const float*)d_in[10];
    const float* mb2  = (const float*)d_in[11];
    float* out = (float*)d_out;

    __nv_bfloat16 *xf, *h1, *m1, *h2;
    float *off, *maskb;
    uint32_t *w1p, *mw1p, *w2p;
    cudaGetSymbolAddress((void**)&xf,    g_xf);
    cudaGetSymbolAddress((void**)&h1,    g_h1);
    cudaGetSymbolAddress((void**)&m1,    g_m1);
    cudaGetSymbolAddress((void**)&h2,    g_h2);
    cudaGetSymbolAddress((void**)&off,   g_off);
    cudaGetSymbolAddress((void**)&maskb, g_mask);
    cudaGetSymbolAddress((void**)&w1p,   g_w1p);
    cudaGetSymbolAddress((void**)&mw1p,  g_mw1p);
    cudaGetSymbolAddress((void**)&w2p,   g_w2p);

    cudaFuncSetAttribute(k_gemm_bf16,
                         cudaFuncAttributeMaxDynamicSharedMemorySize, GEMM_SMEM);

    // 1. layout transform + weight prep (pack bf16 pairs)
    k_transpose<<<dim3(4, 512, 8), dim3(32, 8)>>>(data);
    k_wprep<<<FIN / 2, 256>>>(w1, mw1);
    k_w2prep<<<FC / 2, 256>>>(w2);

    // 2. pool pass 1 -> xf bf16 [n][bin*256+c]
    k_pool<<<NROI * NBIN, 64>>>(rois, nullptr, nullptr, nullptr, xf, 1);

    // 3. G1 fused: xf @ w1 -> h1 (relu) | xf @ mw1 -> m1 (relu)   [bf16 TC]
    k_gemm_bf16<<<dim3(FC / 128, (NROI + 127) / 128, 2), 256, GEMM_SMEM>>>(
        xf, FIN, w1p, b1, h1, FC, mw1p, mb1, m1,
        NROI, FC, FIN, 1);

    // 4. G2: h1 @ w2 -> h2 (relu)   [bf16 TC]
    k_gemm_bf16<<<dim3(FC / 128, (NROI + 127) / 128, 1), 256, GEMM_SMEM>>>(
        h1, FC, w2p, b2, h2, FC, nullptr, nullptr, nullptr,
        NROI, FC, FC, 1);

    // 5. G3: h2 @ w3 -> offsets [2000,98]
    k_head<<<NROI / 8, 256>>>(h2, w3, b3, off, 98, 0);

    // 6. G4: m1 @ mw2 -> mask [2000,49] (sigmoid)
    k_head<<<NROI / 8, 256>>>(m1, mw2, mb2, maskb, 49, 2);

    // 7. pool pass 2 (offset + mask) -> d_out [N,C,7,7]
    k_pool<<<NROI * NBIN, 64>>>(rois, off, maskb, out, nullptr, 2);
}